// round 10
// baseline (speedup 1.0000x reference)
#include <cuda_runtime.h>
#include <cstdint>

// CRPS loss — persistent grid + register double-buffered software pipeline.
//   term1 = mean_i |s_i - y| ; term2 = sum_{i<j}|s_i - s_j| / 256
//   out   = mean_pixels (term1 - term2)
//
// samples: [16, 4, 1, 256, 256] f32 -> 16 planes of 262144 floats
// target:  [4, 1, 256, 256]     f32 -> 262144 floats
//
// 148 CTAs x 256 threads (one CTA per SM). Each thread grid-strides over
// float2 pixel-groups, 3-4 iterations. Next iteration's 17 LDG.64 are issued
// BEFORE current iteration's ~400-instr compute, so steady-state load latency
// is hidden under compute instead of exposed in a lockstep phase.

#define NS      16
#define NPIX    (4 * 1 * 256 * 256)     // 262144
#define NGRP    (NPIX / 2)              // 131072 float2 groups
#define THREADS 256
#define BLOCKS  148
#define STRIDE  (BLOCKS * THREADS)      // 37888

__device__ float        g_partial[BLOCKS];
__device__ unsigned int g_done = 0;

// ---- packed f32x2 helpers (sm_103a) ----
__device__ __forceinline__ uint64_t fadd2(uint64_t a, uint64_t b) {
    uint64_t r; asm("add.rn.f32x2 %0, %1, %2;" : "=l"(r) : "l"(a), "l"(b)); return r;
}
__device__ __forceinline__ uint64_t ffma2(uint64_t a, uint64_t b, uint64_t c) {
    uint64_t r; asm("fma.rn.f32x2 %0, %1, %2, %3;" : "=l"(r) : "l"(a), "l"(b), "l"(c)); return r;
}
__device__ __forceinline__ uint64_t fabs2(uint64_t a) {
    return a & 0x7FFFFFFF7FFFFFFFULL;       // sign-clear both lanes (alu pipe)
}
__device__ __forceinline__ float2 unpack2(uint64_t v) {
    float lo, hi; asm("mov.b64 {%0, %1}, %2;" : "=f"(lo), "=f"(hi) : "l"(v));
    return make_float2(lo, hi);
}
#define NEG_ONE2 0xBF800000BF800000ULL      // {-1.0f, -1.0f}
#define PAIR(acc, a, b) (acc) = fadd2((acc), fabs2(ffma2((b), NEG_ONE2, (a))))

__device__ __forceinline__ void load_group(uint64_t* dst, uint64_t* yv,
                                           const float* __restrict__ samples,
                                           const float* __restrict__ target,
                                           int v)
{
#pragma unroll
    for (int i = 0; i < NS; i++)
        dst[i] = reinterpret_cast<const uint64_t*>(samples + (size_t)i * NPIX)[v];
    *yv = reinterpret_cast<const uint64_t*>(target)[v];
}

__global__ __launch_bounds__(THREADS) void crps_fused_kernel(
    const float* __restrict__ samples,
    const float* __restrict__ target,
    float* __restrict__ out)
{
    const int tid = threadIdx.x;
    const int gid = blockIdx.x * THREADS + tid;

    uint64_t cur[NS], nxt[NS], ycur, ynxt;
    uint64_t t1a = 0, t1b = 0;
    uint64_t t2[4] = {0, 0, 0, 0};

    // prologue: load first group
    int v = gid;
    load_group(cur, &ycur, samples, target, v);

#pragma unroll 1
    for (;;) {
        const int  vn       = v + STRIDE;
        const bool has_next = (vn < NGRP);

        // issue NEXT iteration's loads before this iteration's compute
        load_group(nxt, &ynxt, samples, target, has_next ? vn : gid);

        // ---- compute on cur (packed f32x2; identical math to prior rounds) ----
#pragma unroll
        for (int i = 0; i < NS; i += 2) {
            PAIR(t1a, cur[i],     ycur);
            PAIR(t1b, cur[i + 1], ycur);
        }
        {
            int c = 0;
#pragma unroll
            for (int i = 0; i < NS; i++) {
#pragma unroll
                for (int j = i + 1; j < NS; j++) {
                    PAIR(t2[c & 3], cur[i], cur[j]);
                    c++;
                }
            }
        }

        if (!has_next) break;
        v = vn;
#pragma unroll
        for (int i = 0; i < NS; i++) cur[i] = nxt[i];
        ycur = ynxt;
    }

    const float2 p1 = unpack2(fadd2(t1a, t1b));
    const float2 p2 = unpack2(fadd2(fadd2(t2[0], t2[1]), fadd2(t2[2], t2[3])));
    float val = (p1.x + p1.y) * (1.0f / NS)
              - (p2.x + p2.y) * (1.0f / (NS * NS));

    // ---- block reduction (8 warps) ----
    __shared__ float warp_sum[THREADS / 32];
    float w = val;
#pragma unroll
    for (int off = 16; off > 0; off >>= 1)
        w += __shfl_down_sync(0xFFFFFFFFu, w, off);
    if ((tid & 31) == 0) warp_sum[tid >> 5] = w;
    __syncthreads();

    __shared__ bool is_last;
    if (tid == 0) {
        float b = 0.0f;
#pragma unroll
        for (int k = 0; k < THREADS / 32; k++) b += warp_sum[k];
        g_partial[blockIdx.x] = b;
        __threadfence();
        unsigned int ticket = atomicAdd(&g_done, 1u);
        is_last = (ticket == BLOCKS - 1);
    }
    __syncthreads();

    // ---- last block folds the 148 partials ----
    if (is_last) {
        float acc = (tid < BLOCKS) ? g_partial[tid] : 0.0f;
#pragma unroll
        for (int off = 16; off > 0; off >>= 1)
            acc += __shfl_down_sync(0xFFFFFFFFu, acc, off);
        if ((tid & 31) == 0) warp_sum[tid >> 5] = acc;
        __syncthreads();
        if (tid == 0) {
            float total = 0.0f;
#pragma unroll
            for (int k = 0; k < THREADS / 32; k++) total += warp_sum[k];
            out[0] = total * (1.0f / NPIX);
            g_done = 0;                  // reset for next graph replay
        }
    }
}

extern "C" void kernel_launch(void* const* d_in, const int* in_sizes, int n_in,
                              void* d_out, int out_size)
{
    const float* samples = (const float*)d_in[0];
    const float* target  = (const float*)d_in[1];
    crps_fused_kernel<<<BLOCKS, THREADS>>>(samples, target, (float*)d_out);
}

// round 11
// speedup vs baseline: 1.1373x; 1.1373x over previous
#include <cuda_runtime.h>
#include <cstdint>

// CRPS loss — persistent grid + register double-buffered software pipeline.
//   term1 = mean_i |s_i - y| ; term2 = sum_{i<j}|s_i - s_j| / 256
//   out   = mean_pixels (term1 - term2)
//
// samples: [16, 4, 1, 256, 256] f32 -> 16 planes of 262144 floats
// target:  [4, 1, 256, 256]     f32 -> 262144 floats
//
// 148 CTAs x 256 threads (one CTA per SM). Each thread grid-strides over
// float2 pixel-groups, 3-4 iterations. Next iteration's 17 LDG.64 are issued
// BEFORE current iteration's ~400-instr compute, so steady-state load latency
// is hidden under compute instead of exposed in a lockstep phase.

#define NS      16
#define NPIX    (4 * 1 * 256 * 256)     // 262144
#define NGRP    (NPIX / 2)              // 131072 float2 groups
#define THREADS 256
#define BLOCKS  148
#define STRIDE  (BLOCKS * THREADS)      // 37888

__device__ float        g_partial[BLOCKS];
__device__ unsigned int g_done = 0;

// ---- packed f32x2 helpers (sm_103a) ----
__device__ __forceinline__ uint64_t fadd2(uint64_t a, uint64_t b) {
    uint64_t r; asm("add.rn.f32x2 %0, %1, %2;" : "=l"(r) : "l"(a), "l"(b)); return r;
}
__device__ __forceinline__ uint64_t ffma2(uint64_t a, uint64_t b, uint64_t c) {
    uint64_t r; asm("fma.rn.f32x2 %0, %1, %2, %3;" : "=l"(r) : "l"(a), "l"(b), "l"(c)); return r;
}
__device__ __forceinline__ uint64_t fabs2(uint64_t a) {
    return a & 0x7FFFFFFF7FFFFFFFULL;       // sign-clear both lanes (alu pipe)
}
__device__ __forceinline__ float2 unpack2(uint64_t v) {
    float lo, hi; asm("mov.b64 {%0, %1}, %2;" : "=f"(lo), "=f"(hi) : "l"(v));
    return make_float2(lo, hi);
}
#define NEG_ONE2 0xBF800000BF800000ULL      // {-1.0f, -1.0f}
#define PAIR(acc, a, b) (acc) = fadd2((acc), fabs2(ffma2((b), NEG_ONE2, (a))))

__device__ __forceinline__ void load_group(uint64_t* dst, uint64_t* yv,
                                           const float* __restrict__ samples,
                                           const float* __restrict__ target,
                                           int v)
{
#pragma unroll
    for (int i = 0; i < NS; i++)
        dst[i] = reinterpret_cast<const uint64_t*>(samples + (size_t)i * NPIX)[v];
    *yv = reinterpret_cast<const uint64_t*>(target)[v];
}

__global__ __launch_bounds__(THREADS) void crps_fused_kernel(
    const float* __restrict__ samples,
    const float* __restrict__ target,
    float* __restrict__ out)
{
    const int tid = threadIdx.x;
    const int gid = blockIdx.x * THREADS + tid;

    uint64_t cur[NS], nxt[NS], ycur, ynxt;
    uint64_t t1a = 0, t1b = 0;
    uint64_t t2[4] = {0, 0, 0, 0};

    // prologue: load first group
    int v = gid;
    load_group(cur, &ycur, samples, target, v);

#pragma unroll 1
    for (;;) {
        const int  vn       = v + STRIDE;
        const bool has_next = (vn < NGRP);

        // issue NEXT iteration's loads before this iteration's compute
        load_group(nxt, &ynxt, samples, target, has_next ? vn : gid);

        // ---- compute on cur (packed f32x2; identical math to prior rounds) ----
#pragma unroll
        for (int i = 0; i < NS; i += 2) {
            PAIR(t1a, cur[i],     ycur);
            PAIR(t1b, cur[i + 1], ycur);
        }
        {
            int c = 0;
#pragma unroll
            for (int i = 0; i < NS; i++) {
#pragma unroll
                for (int j = i + 1; j < NS; j++) {
                    PAIR(t2[c & 3], cur[i], cur[j]);
                    c++;
                }
            }
        }

        if (!has_next) break;
        v = vn;
#pragma unroll
        for (int i = 0; i < NS; i++) cur[i] = nxt[i];
        ycur = ynxt;
    }

    const float2 p1 = unpack2(fadd2(t1a, t1b));
    const float2 p2 = unpack2(fadd2(fadd2(t2[0], t2[1]), fadd2(t2[2], t2[3])));
    float val = (p1.x + p1.y) * (1.0f / NS)
              - (p2.x + p2.y) * (1.0f / (NS * NS));

    // ---- block reduction (8 warps) ----
    __shared__ float warp_sum[THREADS / 32];
    float w = val;
#pragma unroll
    for (int off = 16; off > 0; off >>= 1)
        w += __shfl_down_sync(0xFFFFFFFFu, w, off);
    if ((tid & 31) == 0) warp_sum[tid >> 5] = w;
    __syncthreads();

    __shared__ bool is_last;
    if (tid == 0) {
        float b = 0.0f;
#pragma unroll
        for (int k = 0; k < THREADS / 32; k++) b += warp_sum[k];
        g_partial[blockIdx.x] = b;
        __threadfence();
        unsigned int ticket = atomicAdd(&g_done, 1u);
        is_last = (ticket == BLOCKS - 1);
    }
    __syncthreads();

    // ---- last block folds the 148 partials ----
    if (is_last) {
        float acc = (tid < BLOCKS) ? g_partial[tid] : 0.0f;
#pragma unroll
        for (int off = 16; off > 0; off >>= 1)
            acc += __shfl_down_sync(0xFFFFFFFFu, acc, off);
        if ((tid & 31) == 0) warp_sum[tid >> 5] = acc;
        __syncthreads();
        if (tid == 0) {
            float total = 0.0f;
#pragma unroll
            for (int k = 0; k < THREADS / 32; k++) total += warp_sum[k];
            out[0] = total * (1.0f / NPIX);
            g_done = 0;                  // reset for next graph replay
        }
    }
}

extern "C" void kernel_launch(void* const* d_in, const int* in_sizes, int n_in,
                              void* d_out, int out_size)
{
    const float* samples = (const float*)d_in[0];
    const float* target  = (const float*)d_in[1];
    crps_fused_kernel<<<BLOCKS, THREADS>>>(samples, target, (float*)d_out);
}